// round 4
// baseline (speedup 1.0000x reference)
#include <cuda_runtime.h>
#include <cstdint>

// KVGather: out[n,i,k,w,c] = r_weight[n,i,k] * kv[n, r_idx[n,i,k], w, c]
// N=16, P2=64, TOPK=8, W2=64, C_KV=512
// Output: 1 GiB fp32 stream -> HBM-write-bound. kv 128 MiB, per-n hot set
// 8 MiB -> reads should be L2 hits; pin them with 256-bit L2::evict_last
// loads (ptxas on sm_103a requires .v8.b32 for the evict_last modifier).

#define KVG_N     16
#define KVG_P2    64
#define KVG_TOPK  8
#define KVG_W2    64
#define KVG_CKV   512

#define NUM_TILES   (KVG_N * KVG_P2 * KVG_TOPK)      // 8192
#define TILE_F8     (KVG_W2 * KVG_CKV / 8)           // 4096 float8 per tile (128 KB)
#define F8_PER_THR  4
#define THREADS     256
#define F8_PER_BLK  (F8_PER_THR * THREADS)           // 1024
#define BLKS_PER_TILE (TILE_F8 / F8_PER_BLK)         // 4
#define GRID        (NUM_TILES * BLKS_PER_TILE)      // 32768

struct f8 { float4 a, b; };

// 256-bit load with L2 evict-last policy: keep the hot kv region resident in
// L2 while the 1 GiB output stream (evict-first stores) flows past it.
__device__ __forceinline__ f8 ldg256_el(const void* p) {
    f8 v;
    asm("ld.global.nc.L2::evict_last.v8.b32 "
        "{%0,%1,%2,%3,%4,%5,%6,%7}, [%8];"
        : "=f"(v.a.x), "=f"(v.a.y), "=f"(v.a.z), "=f"(v.a.w),
          "=f"(v.b.x), "=f"(v.b.y), "=f"(v.b.z), "=f"(v.b.w)
        : "l"(p));
    return v;
}

__global__ __launch_bounds__(THREADS, 8)
void kvg_gather_kernel(const float* __restrict__ kv,
                       const float* __restrict__ r_weight,
                       const void*  __restrict__ r_idx,
                       float4*      __restrict__ out) {
    const int bid   = blockIdx.x;
    const int tile  = bid >> 2;            // BLKS_PER_TILE = 4
    const int chunk = bid & 3;
    const int n     = tile >> 9;           // / (P2*TOPK)

    // ---- int64-vs-int32 index-width detection, fused in-kernel ----
    // View r_idx as int32 words. int64 values in [0,64) -> every odd word 0.
    // int32 indices -> OR of 32 odd words nonzero w.p. 1-(1/64)^32.
    // Words [1..63] in-bounds for both layouts; L2-hot, ~free.
    const int lane = threadIdx.x & 31;
    unsigned probe = ((const unsigned*)r_idx)[2 * lane + 1];
    unsigned odd_or = __reduce_or_sync(0xffffffffu, probe);
    const bool is64 = (odd_or == 0u);

    long long idx;
    if (is64) idx = ((const long long*)r_idx)[tile];
    else      idx = (long long)((const int*)r_idx)[tile];

    const float wt = r_weight[tile];

    const float* __restrict__ src =
        kv + ((long long)n * KVG_P2 + idx) * (long long)(KVG_W2 * KVG_CKV);
    float4* __restrict__ dst = out + (long long)tile * (long long)(TILE_F8 * 2);

    // Each thread: 4 x 256-bit loads, consecutive pair of float4 per load.
    const int base_f8 = chunk * F8_PER_BLK + threadIdx.x;

#pragma unroll
    for (int j = 0; j < F8_PER_THR; j++) {
        const int p = base_f8 + j * THREADS;        // float8 index
        f8 v = ldg256_el(src + (long long)p * 8);
        v.a.x *= wt; v.a.y *= wt; v.a.z *= wt; v.a.w *= wt;
        v.b.x *= wt; v.b.y *= wt; v.b.z *= wt; v.b.w *= wt;
        // Streaming 128-bit stores: write-once 1 GiB stream, evict-first.
        __stcs(&dst[2 * p],     v.a);
        __stcs(&dst[2 * p + 1], v.b);
    }
}

extern "C" void kernel_launch(void* const* d_in, const int* in_sizes, int n_in,
                              void* d_out, int out_size) {
    // metadata order: r_idx, r_weight, kv
    const void*  r_idx    = d_in[0];
    const float* r_weight = (const float*)d_in[1];
    const float* kv       = (const float*)d_in[2];
    float4* out           = (float4*)d_out;

    kvg_gather_kernel<<<GRID, THREADS>>>(kv, r_weight, r_idx, out);
}

// round 5
// speedup vs baseline: 1.5699x; 1.5699x over previous
#include <cuda_runtime.h>
#include <cstdint>

// KVGather: out[n,i,k,w,c] = r_weight[n,i,k] * kv[n, r_idx[n,i,k], w, c]
// N=16, P2=64, TOPK=8, W2=64, C_KV=512
// Output 1 GiB fp32 + 128 MiB compulsory reads -> DRAM traffic is already at
// the compulsory floor (R1 measured ~1.15 GB vs 1.20 GB minimum). The kernel
// is bound purely by achieved HBM bandwidth; R1's 128-bit __ldg + __stcs path
// achieved 82.8% of peak. Keep that path; fuse the dtype-detect launch away.

#define KVG_N     16
#define KVG_P2    64
#define KVG_TOPK  8
#define KVG_W2    64
#define KVG_CKV   512

#define NUM_TILES   (KVG_N * KVG_P2 * KVG_TOPK)      // 8192
#define TILE_F4     (KVG_W2 * KVG_CKV / 4)           // 8192 float4 per tile (128 KB)
#define F4_PER_THR  8
#define THREADS     256
#define F4_PER_BLK  (F4_PER_THR * THREADS)           // 2048
#define BLKS_PER_TILE (TILE_F4 / F4_PER_BLK)         // 4
#define GRID        (NUM_TILES * BLKS_PER_TILE)      // 32768

__global__ __launch_bounds__(THREADS, 8)
void kvg_gather_kernel(const float4* __restrict__ kv,
                       const float*  __restrict__ r_weight,
                       const void*   __restrict__ r_idx,
                       float4*       __restrict__ out) {
    const int bid   = blockIdx.x;
    const int tile  = bid >> 2;            // BLKS_PER_TILE = 4
    const int chunk = bid & 3;
    const int n     = tile >> 9;           // / (P2*TOPK)

    // ---- int64-vs-int32 index-width detection, fused in-kernel ----
    // View r_idx as int32 words. int64 values in [0,64) -> every odd word 0.
    // int32 indices -> OR of 32 odd words nonzero w.p. 1-(1/64)^32.
    // Words [1..63] are in-bounds for both layouts (int32 layout = 8192
    // words); the two touched sectors are L2-hot after the first blocks.
    const int lane = threadIdx.x & 31;
    unsigned probe = ((const unsigned*)r_idx)[2 * lane + 1];
    unsigned odd_or = __reduce_or_sync(0xffffffffu, probe);
    const bool is64 = (odd_or == 0u);

    long long idx;
    if (is64) idx = ((const long long*)r_idx)[tile];
    else      idx = (long long)((const int*)r_idx)[tile];

    const float wt = r_weight[tile];

    const float4* __restrict__ src =
        kv + ((long long)n * KVG_P2 + idx) * (long long)TILE_F4;
    float4* __restrict__ dst = out + (long long)tile * (long long)TILE_F4;

    const int base = chunk * F4_PER_BLK + threadIdx.x;

#pragma unroll
    for (int j = 0; j < F4_PER_THR; j++) {
        const int p = base + j * THREADS;
        float4 v = __ldg(&src[p]);
        v.x *= wt; v.y *= wt; v.z *= wt; v.w *= wt;
        // Streaming store: write-once 1 GiB stream, evict-first keeps the
        // hot 8 MiB kv read set resident in L2.
        __stcs(&dst[p], v);
    }
}

extern "C" void kernel_launch(void* const* d_in, const int* in_sizes, int n_in,
                              void* d_out, int out_size) {
    // metadata order: r_idx, r_weight, kv
    const void*  r_idx    = d_in[0];
    const float* r_weight = (const float*)d_in[1];
    const float4* kv      = (const float4*)d_in[2];
    float4* out           = (float4*)d_out;

    kvg_gather_kernel<<<GRID, THREADS>>>(kv, r_weight, r_idx, out);
}